// round 10
// baseline (speedup 1.0000x reference)
#include <cuda_runtime.h>

// ---------------------------------------------------------------------------
// LDPC damped sum-product BP, GB300 — single persistent kernel.
//   N_VAR=8192, N_CHK=4096, DV=3 (edge e = 3*v + j), BATCH=128, T=30.
//
// One launch. Software grid barriers (one-wave residency guaranteed by sizing
// the grid from the occupancy API). Batch is split into two independent
// groups (float4 lanes 0-15 / 16-31) with separate barriers so the
// memory-bound variable phase of one group overlaps the MUFU-bound check
// phase of the other on the same SMs.
//
// Check message uses the R4-validated formulation (ext = P/f, clip,
// log((1+ext)/(1-ext))): it reproduces the reference's 1±ext cancellation
// pattern so near-pole rounding stays CORRELATED with the reference
// (R4 measured rel_err 3.8e-7; the merged-ratio variant decorrelated the
// pole cancellation and failed at 5.9e-3).
// ---------------------------------------------------------------------------

#define NVAR  8192
#define NCHK  4096
#define NE    (NVAR * 3)          // 24576
#define BB    128
#define TITER 30
#define EPSV  1e-7f
#define NT    512                 // threads per block

// ---- scratch state (no allocation allowed -> device globals) --------------
__device__ __align__(16) float g_msgC2V[NE * BB];
__device__ __align__(16) float g_msgV2C[NE * BB];
__device__ int g_cnt[NCHK];
__device__ int g_off[NCHK + 1];
__device__ int g_cur[NCHK];
__device__ int g_edges[NE];

// barrier state: [0]=global, [1]=group0, [2]=group1 (padded 128B apart)
__device__ volatile unsigned g_gen[3 * 32];
__device__ unsigned          g_arr[3 * 32];

__device__ __forceinline__ void grid_bar(int which, unsigned nb) {
    __syncthreads();
    if (threadIdx.x == 0) {
        volatile unsigned* gen = &g_gen[which * 32];
        unsigned*          cnt = &g_arr[which * 32];
        __threadfence();                       // release prior writes
        unsigned g0 = *gen;
        if (atomicAdd(cnt, 1u) == nb - 1u) {   // last to arrive
            atomicExch(cnt, 0u);               // reset BEFORE flipping gen
            __threadfence();
            *gen = g0 + 1u;
        } else {
            while (*gen == g0) { __nanosleep(64); }
        }
        __threadfence();                       // acquire (CCTL.IVALL: L1 inval)
    }
    __syncthreads();
}

// tanh(clip(x,-15,15)/2) with reference's sign/magnitude-floor semantics
__device__ __forceinline__ float fmsg(float x) {
    x = fminf(fmaxf(x, -15.0f), 15.0f);
    float E = __expf(-fabsf(x));                       // e^{-|x|}
    float m = __fdividef(1.0f - E, 1.0f + E);          // tanh(|x|/2)
    m = fmaxf(m, EPSV);
    return (x < 0.0f) ? -m : m;                        // (t < 0) sign rule
}

// check->variable message: 2*atanh(clip(P/f)) — R4-validated form.
__device__ __forceinline__ float cmsg(float f, float P) {
    float ext = __fdividef(P, f);
    ext = fminf(fmaxf(ext, -1.0f + EPSV), 1.0f - EPSV);
    return __logf(__fdividef(1.0f + ext, 1.0f - ext));
}

__device__ __forceinline__ float4 add4(float4 a, float4 b) {
    return make_float4(a.x + b.x, a.y + b.y, a.z + b.z, a.w + b.w);
}

// ---------------------------------------------------------------------------
__global__ void __launch_bounds__(NT) bp_k(const float* __restrict__ chn,
                                           const float* __restrict__ gl,
                                           const int*   __restrict__ echk,
                                           float*       __restrict__ out,
                                           unsigned nbtot, unsigned nbg) {
    const int      tid  = threadIdx.x;
    const unsigned gtid = blockIdx.x * NT + tid;
    const unsigned nthr = nbtot * NT;

    // ================= CSR build for the check side (global phases) ========
    for (unsigned i = gtid; i < NCHK; i += nthr) g_cnt[i] = 0;
    grid_bar(0, nbtot);
    for (unsigned e = gtid; e < NE; e += nthr) atomicAdd(&g_cnt[echk[e]], 1);
    grid_bar(0, nbtot);
    if (blockIdx.x == 0) {                 // exclusive scan (block 0 only)
        __shared__ int sh[NT];
        int loc[8], s = 0;
#pragma unroll
        for (int k = 0; k < 8; k++) { loc[k] = g_cnt[tid * 8 + k]; s += loc[k]; }
        sh[tid] = s;
        __syncthreads();
        for (int off = 1; off < NT; off <<= 1) {
            int v = (tid >= off) ? sh[tid - off] : 0;
            __syncthreads();
            sh[tid] += v;
            __syncthreads();
        }
        int run = sh[tid] - s;
#pragma unroll
        for (int k = 0; k < 8; k++) {
            g_off[tid * 8 + k] = run; g_cur[tid * 8 + k] = run; run += loc[k];
        }
        if (tid == NT - 1) g_off[NCHK] = run;      // == NE
    }
    grid_bar(0, nbtot);
    for (unsigned e = gtid; e < NE; e += nthr) {
        int p = atomicAdd(&g_cur[echk[e]], 1);
        g_edges[p] = e;
    }
    grid_bar(0, nbtot);
    // sort each check's edge list (deterministic order across replays)
    for (unsigned c = gtid; c < NCHK; c += nthr) {
        int s = g_off[c], en = g_off[c + 1];
        for (int i = s + 1; i < en; i++) {
            int key = g_edges[i], j = i - 1;
            while (j >= s && g_edges[j] > key) { g_edges[j + 1] = g_edges[j]; j--; }
            g_edges[j + 1] = key;
        }
    }
    grid_bar(0, nbtot);

    // ================= main loop: two independent batch groups =============
    const int      grp   = blockIdx.x & 1;          // lanes [grp*16, grp*16+16)
    const unsigned gt    = (blockIdx.x >> 1) * NT + tid;
    const unsigned gstr  = nbg * NT;
    const int      barid = 1 + grp;
    const float    gam   = 1.0f / (1.0f + __expf(-gl[0]));   // sigmoid
    const float    omg   = 1.0f - gam;

    const float4* CHN = (const float4*)chn;
    float4*       V2C = (float4*)g_msgV2C;
    float4*       C2V = (float4*)g_msgC2V;
    float4*       OUT = (float4*)out;

    const unsigned NW_VAR = NVAR * 16;   // (variable, lane-in-group)
    const unsigned NW_CHK = NCHK * 16;   // (check,    lane-in-group)
    const float4   Z4     = make_float4(0.f, 0.f, 0.f, 0.f);

    for (int it = 0; it < TITER; ++it) {
        // -------- variable -> check phase (also emits prev posterior) ------
        for (unsigned w = gt; w < NW_VAR; w += gstr) {
            int v    = (int)(w >> 4);
            int l    = (int)(w & 15) + (grp << 4);
            int base = v * 96 + l;                   // 3 rows * 32 f4/row
            float4 c0 = Z4, c1 = Z4, c2 = Z4;
            if (it) { c0 = C2V[base]; c1 = C2V[base + 32]; c2 = C2V[base + 64]; }
            float4 ch = CHN[v * 32 + l];
            float4 vs = add4(add4(c0, c1), c2);
            if (it)  // posterior of iteration it-1, free (operands in hand)
                OUT[(size_t)(it - 1) * NVAR * 32 + v * 32 + l] = add4(ch, vs);
            float4 tot = add4(ch, vs);
#pragma unroll
            for (int j = 0; j < 3; j++) {
                float4 cj  = (j == 0) ? c0 : ((j == 1) ? c1 : c2);
                int    idx = base + j * 32;
                float4 old = it ? V2C[idx] : Z4;
                float4 nv;
                nv.x = gam * (tot.x - cj.x) + omg * old.x;
                nv.y = gam * (tot.y - cj.y) + omg * old.y;
                nv.z = gam * (tot.z - cj.z) + omg * old.z;
                nv.w = gam * (tot.w - cj.w) + omg * old.w;
                V2C[idx] = nv;
            }
        }
        grid_bar(barid, nbg);

        // -------- check -> variable phase ----------------------------------
        for (unsigned w = gt; w < NW_CHK; w += gstr) {
            int c = (int)(w >> 4);
            int l = (int)(w & 15) + (grp << 4);
            int s = g_off[c], en = g_off[c + 1];
            float4 P = make_float4(1.f, 1.f, 1.f, 1.f);
            for (int i = s; i < en; i++) {           // signed product
                int    eid = g_edges[i];
                float4 x   = V2C[eid * 32 + l];
                P.x *= fmsg(x.x); P.y *= fmsg(x.y);
                P.z *= fmsg(x.z); P.w *= fmsg(x.w);
            }
            for (int i = s; i < en; i++) {           // extrinsic + 2*atanh
                int    eid = g_edges[i];
                float4 x   = V2C[eid * 32 + l];      // L1 hit (just read)
                float4 m;
                m.x = cmsg(fmsg(x.x), P.x);
                m.y = cmsg(fmsg(x.y), P.y);
                m.z = cmsg(fmsg(x.z), P.z);
                m.w = cmsg(fmsg(x.w), P.w);
                C2V[eid * 32 + l] = m;
            }
        }
        grid_bar(barid, nbg);
    }

    // -------- epilogue: posterior of the final iteration -------------------
    for (unsigned w = gt; w < NW_VAR; w += gstr) {
        int v    = (int)(w >> 4);
        int l    = (int)(w & 15) + (grp << 4);
        int base = v * 96 + l;
        float4 ssum = add4(add4(C2V[base], C2V[base + 32]), C2V[base + 64]);
        OUT[(size_t)(TITER - 1) * NVAR * 32 + v * 32 + l] =
            add4(CHN[v * 32 + l], ssum);
    }
}

// ---------------------------------------------------------------------------
extern "C" void kernel_launch(void* const* d_in, const int* in_sizes, int n_in,
                              void* d_out, int out_size) {
    (void)in_sizes; (void)n_in; (void)out_size;
    const float* chn  = (const float*)d_in[0];   // (8192, 128) f32
    const float* gl   = (const float*)d_in[1];   // (1,)        f32
    const int*   echk = (const int*)d_in[3];     // (24576,)    i32
    float*       out  = (float*)d_out;           // (30, 8192, 128) f32

    // One-wave grid sizing: all blocks must be co-resident for the barrier.
    int dev = 0, sms = 0, occ = 0;
    cudaGetDevice(&dev);
    cudaDeviceGetAttribute(&sms, cudaDevAttrMultiProcessorCount, dev);
    cudaOccupancyMaxActiveBlocksPerMultiprocessor(&occ, bp_k, NT, 0);
    if (occ < 1) occ = 1;
    int nb = sms * occ;
    if (nb & 1) nb--;            // even split across the two batch groups
    if (nb < 2) nb = 2;

    bp_k<<<nb, NT>>>(chn, gl, echk, out, (unsigned)nb, (unsigned)(nb / 2));
}

// round 14
// speedup vs baseline: 1.6780x; 1.6780x over previous
#include <cuda_runtime.h>

// ---------------------------------------------------------------------------
// LDPC damped sum-product BP, GB300 — multi-kernel, check-sorted layout.
//   N_VAR=8192, N_CHK=4096, DV=3 (edge e = 3*v + j), BATCH=128, T=30.
//
// Layout: f (tanh values) and C2V messages live in CHECK-CSR SLOT ORDER.
//   - check phase: all reads/writes contiguous (slot rows adjacent), no index
//     loads, no random gathers -> streaming + L1-hit second pass.
//   - variable phase: 3 independent gather reads (C2V) + scatter writes (f),
//     via perm[e] = CSR slot of edge e. Independent loads overlap; stores
//     don't stall. V2C (damping state) stays in var order (fully linear).
//
// One warp handles one full 128-float batch row (32 x float4): every global
// access is a coalesced 512B transaction.
//
// Math identical to the R4/R6-validated formulation:
//   f   = sign * max(tanh(clip(V2C,-15,15)/2), eps)      (computed in var)
//   P   = prod f ; ext = clip(P/f, +/-(1-eps)) ; msg = log((1+ext)/(1-ext))
//   out[t] = chn + sum_j C2V  (emitted by next var phase / final epilogue)
// ---------------------------------------------------------------------------

#define NVAR  8192
#define NCHK  4096
#define NE    (NVAR * 3)          // 24576
#define TITER 30
#define EPSV  1e-7f

// ---- scratch state (no allocation allowed -> device globals) --------------
__device__ __align__(16) float g_C2V[NE * 128];   // check-slot order
__device__ __align__(16) float g_F  [NE * 128];   // check-slot order
__device__ __align__(16) float g_V2C[NE * 128];   // var/edge order (linear)
__device__ int g_cnt[NCHK];
__device__ int g_off[NCHK + 1];
__device__ int g_cur[NCHK];
__device__ int g_edges[NE];       // edge ids per check (sorted -> determinism)
__device__ int g_perm[NE];        // edge id -> CSR slot

// ---------------------------------------------------------------------------
// CSR build (5 tiny kernels, ~15us total, once per launch)
// ---------------------------------------------------------------------------
__global__ void zero_k() {
    int i = blockIdx.x * blockDim.x + threadIdx.x;
    if (i < NCHK) g_cnt[i] = 0;
}
__global__ void hist_k(const int* __restrict__ echk) {
    int e = blockIdx.x * blockDim.x + threadIdx.x;
    if (e < NE) atomicAdd(&g_cnt[echk[e]], 1);
}
__global__ void scan_k() {   // single block, 1024 threads, 4 counts each
    __shared__ int sh[1024];
    int t = threadIdx.x;
    int c0 = g_cnt[4*t+0], c1 = g_cnt[4*t+1], c2 = g_cnt[4*t+2], c3 = g_cnt[4*t+3];
    int s = c0 + c1 + c2 + c3;
    sh[t] = s;
    __syncthreads();
    for (int off = 1; off < 1024; off <<= 1) {
        int v = (t >= off) ? sh[t - off] : 0;
        __syncthreads();
        sh[t] += v;
        __syncthreads();
    }
    int o = sh[t] - s;
    g_off[4*t+0] = o; g_cur[4*t+0] = o; o += c0;
    g_off[4*t+1] = o; g_cur[4*t+1] = o; o += c1;
    g_off[4*t+2] = o; g_cur[4*t+2] = o; o += c2;
    g_off[4*t+3] = o; g_cur[4*t+3] = o; o += c3;
    if (t == 1023) g_off[NCHK] = o;      // == NE
}
__global__ void scat_k(const int* __restrict__ echk) {
    int e = blockIdx.x * blockDim.x + threadIdx.x;
    if (e < NE) g_edges[atomicAdd(&g_cur[echk[e]], 1)] = e;
}
__global__ void sortperm_k() {   // per-check insertion sort + inverse perm
    int c = blockIdx.x * blockDim.x + threadIdx.x;
    if (c >= NCHK) return;
    int s = g_off[c], en = g_off[c + 1];
    for (int i = s + 1; i < en; i++) {
        int key = g_edges[i], j = i - 1;
        while (j >= s && g_edges[j] > key) { g_edges[j + 1] = g_edges[j]; j--; }
        g_edges[j + 1] = key;
    }
    for (int i = s; i < en; i++) g_perm[g_edges[i]] = i;
}

// ---------------------------------------------------------------------------
__device__ __forceinline__ float4 add4(float4 a, float4 b) {
    return make_float4(a.x + b.x, a.y + b.y, a.z + b.z, a.w + b.w);
}

// f = sign * max(tanh(clip(x,-15,15)/2), eps); exp-form keeps 1-|t| exact
// near saturation (pole-correlated with the reference -- validated).
__device__ __forceinline__ float fmsg(float x) {
    x = fminf(fmaxf(x, -15.0f), 15.0f);
    float E = __expf(-fabsf(x));
    float m = __fdividef(1.0f - E, 1.0f + E);
    m = fmaxf(m, EPSV);
    return (x < 0.0f) ? -m : m;
}
__device__ __forceinline__ float4 fmsg4(float4 x) {
    return make_float4(fmsg(x.x), fmsg(x.y), fmsg(x.z), fmsg(x.w));
}
// msg = 2*atanh(clip(P/f)) — R4-validated three-step form.
__device__ __forceinline__ float cmsg(float f, float P) {
    float ext = __fdividef(P, f);
    ext = fminf(fmaxf(ext, -1.0f + EPSV), 1.0f - EPSV);
    return __logf(__fdividef(1.0f + ext, 1.0f - ext));
}

// ---------------------------------------------------------------------------
// Variable phase: warp per variable (32 lanes x float4 = 128-float row).
// Gathers C2V from 3 CSR slots, emits prev posterior, damps V2C (linear),
// scatters f to the same 3 slots.  16 vars/block, 512 blocks.
// ---------------------------------------------------------------------------
template <bool FIRST>
__global__ void __launch_bounds__(512) var_k(const float* __restrict__ chn,
                                             const float* __restrict__ gl,
                                             float* __restrict__ outp) {
    const int w = threadIdx.x >> 5;            // warp in block
    const int l = threadIdx.x & 31;            // float4 lane
    const int v = blockIdx.x * 16 + w;
    const float gam = 1.0f / (1.0f + __expf(-gl[0]));
    const float omg = 1.0f - gam;

    const float4* CHN = (const float4*)chn;
    float4*       C2V = (float4*)g_C2V;
    float4*       F   = (float4*)g_F;
    float4*       V2C = (float4*)g_V2C;

    const int p0 = g_perm[3 * v + 0];          // lane-uniform broadcasts
    const int p1 = g_perm[3 * v + 1];
    const int p2 = g_perm[3 * v + 2];

    const float4 Z4 = make_float4(0.f, 0.f, 0.f, 0.f);
    float4 c0 = Z4, c1 = Z4, c2 = Z4;
    if (!FIRST) {                              // 3 independent gathers
        c0 = C2V[p0 * 32 + l];
        c1 = C2V[p1 * 32 + l];
        c2 = C2V[p2 * 32 + l];
    }
    float4 ch  = CHN[v * 32 + l];
    float4 tot = add4(ch, add4(add4(c0, c1), c2));
    if (!FIRST)                                // posterior of prev iteration
        ((float4*)outp)[v * 32 + l] = tot;

#pragma unroll
    for (int j = 0; j < 3; j++) {
        float4 cj = (j == 0) ? c0 : ((j == 1) ? c1 : c2);
        int    pj = (j == 0) ? p0 : ((j == 1) ? p1 : p2);
        int    li = (3 * v + j) * 32 + l;      // linear V2C index
        float4 old = FIRST ? Z4 : V2C[li];
        float4 nv;
        nv.x = gam * (tot.x - cj.x) + omg * old.x;
        nv.y = gam * (tot.y - cj.y) + omg * old.y;
        nv.z = gam * (tot.z - cj.z) + omg * old.z;
        nv.w = gam * (tot.w - cj.w) + omg * old.w;
        V2C[li] = nv;
        F[pj * 32 + l] = fmsg4(nv);            // scatter (stores don't stall)
    }
}

// ---------------------------------------------------------------------------
// Check phase: warp per check; slot rows contiguous -> streaming loads.
// Pass 1 signed product; pass 2 (L1 hits) extrinsic + 2*atanh.
// 16 checks/block, 256 blocks.
// ---------------------------------------------------------------------------
__global__ void __launch_bounds__(512) chk_k() {
    const int w = threadIdx.x >> 5;
    const int l = threadIdx.x & 31;
    const int c = blockIdx.x * 16 + w;
    const int s  = g_off[c];
    const int en = g_off[c + 1];

    const float4* F   = (const float4*)g_F;
    float4*       C2V = (float4*)g_C2V;

    float4 P = make_float4(1.f, 1.f, 1.f, 1.f);
#pragma unroll 4
    for (int i = s; i < en; i++) {             // contiguous rows
        float4 f = F[i * 32 + l];
        P.x *= f.x; P.y *= f.y; P.z *= f.z; P.w *= f.w;
    }
#pragma unroll 4
    for (int i = s; i < en; i++) {
        float4 f = F[i * 32 + l];              // L1 hit
        float4 m;
        m.x = cmsg(f.x, P.x);
        m.y = cmsg(f.y, P.y);
        m.z = cmsg(f.z, P.z);
        m.w = cmsg(f.w, P.w);
        C2V[i * 32 + l] = m;                   // contiguous store
    }
}

// Final posterior (iteration T-1): same gather pattern as var_k's prologue.
__global__ void __launch_bounds__(512) out_k(const float* __restrict__ chn,
                                             float* __restrict__ outp) {
    const int w = threadIdx.x >> 5;
    const int l = threadIdx.x & 31;
    const int v = blockIdx.x * 16 + w;
    const float4* C2V = (const float4*)g_C2V;
    float4 c0 = C2V[g_perm[3 * v + 0] * 32 + l];
    float4 c1 = C2V[g_perm[3 * v + 1] * 32 + l];
    float4 c2 = C2V[g_perm[3 * v + 2] * 32 + l];
    ((float4*)outp)[v * 32 + l] =
        add4(((const float4*)chn)[v * 32 + l], add4(add4(c0, c1), c2));
}

// ---------------------------------------------------------------------------
extern "C" void kernel_launch(void* const* d_in, const int* in_sizes, int n_in,
                              void* d_out, int out_size) {
    (void)in_sizes; (void)n_in; (void)out_size;
    const float* chn  = (const float*)d_in[0];   // (8192, 128) f32
    const float* gl   = (const float*)d_in[1];   // (1,)        f32
    const int*   echk = (const int*)d_in[3];     // (24576,)    i32
    float*       out  = (float*)d_out;           // (30, 8192, 128) f32

    // CSR + perm build
    zero_k    <<<(NCHK + 255) / 256, 256>>>();
    hist_k    <<<(NE   + 255) / 256, 256>>>(echk);
    scan_k    <<<1, 1024>>>();
    scat_k    <<<(NE   + 255) / 256, 256>>>(echk);
    sortperm_k<<<(NCHK + 255) / 256, 256>>>();

    const size_t OSZ = (size_t)NVAR * 128;
    var_k<true><<<NVAR / 16, 512>>>(chn, gl, nullptr);
    chk_k      <<<NCHK / 16, 512>>>();
    for (int t = 1; t < TITER; t++) {
        var_k<false><<<NVAR / 16, 512>>>(chn, gl, out + (size_t)(t - 1) * OSZ);
        chk_k      <<<NCHK / 16, 512>>>();
    }
    out_k<<<NVAR / 16, 512>>>(chn, out + (size_t)(TITER - 1) * OSZ);
}